// round 7
// baseline (speedup 1.0000x reference)
#include <cuda_runtime.h>

#define NC 16       // codebooks
#define NK 16       // prototypes per codebook
#define NM 16       // output rows (M)
#define ND 64       // feature dim
#define NDP 65      // padded A row stride: bank=(r+d)%32 -> conflict-free encode reads
#define NSPL 4      // tree depth
#define LSTR 20     // LUT row stride: conflict-free LDS.128 gather
#define TB 128      // threads = rows per tile

__device__ float g_lut[NC * NK * NM];
__device__ volatile int g_lut_ready;   // zero-init; idempotent across graph replays

__device__ __forceinline__ void fadd2(unsigned long long& a, unsigned long long b) {
    asm("add.rn.f32x2 %0, %0, %1;" : "+l"(a) : "l"(b));
}

// ---------------------------------------------------------------------------
// Single fused kernel.
//   block 0            : LUT producer (lut[c,k,m] = sum_d B[m,d]*P[c,k,d]),
//                        then threadfence + flag. Runs while tiles encode.
//   blocks 1..ntiles   : stage A -> encode (code in register) -> wait flag ->
//                        stage LUT -> gather -> store. 4 CTAs/SM.
// ---------------------------------------------------------------------------
__global__ void __launch_bounds__(TB, 4) fused_kernel(
    const float* __restrict__ A,
    const float* __restrict__ B,        // [M,D]
    const float* __restrict__ P,        // [C,K,D]
    const int*   __restrict__ sdim_g,   // [C,NSPL]
    const float* __restrict__ sval_g,   // [C,NSPL,8]
    float*       __restrict__ out,      // [M,N]
    int N)
{
    extern __shared__ float smem[];
    float* As     = smem;                       // TB*NDP = 8320 floats
    float* lut_s  = As + TB * NDP;              // 5120 floats
    float* sval16 = lut_s + NC * NK * LSTR;     // 256 floats
    int*   sdim   = (int*)(sval16 + NC * 16);   // 64 ints      -> 55040 B total

    const int tid = threadIdx.x;

    if (blockIdx.x == 0) {
        // ---- LUT producer ----
        float* Bs = As;                          // [NM][NDP]
        for (int i = tid; i < NM * ND; i += TB)
            Bs[(i >> 6) * NDP + (i & 63)] = B[i];
        __syncthreads();
#pragma unroll
        for (int e = 0; e < 2; e++) {
            int ck = e * TB + tid;               // (c,k) pair 0..255
            const float4* Pr = (const float4*)(P + ck * ND);
            float4 pr[16];
#pragma unroll
            for (int j = 0; j < 16; j++) pr[j] = Pr[j];
#pragma unroll
            for (int m = 0; m < NM; m++) {
                const float* br = Bs + m * NDP;  // broadcast reads
                float acc = 0.f;
#pragma unroll
                for (int j = 0; j < 16; j++) {
                    acc = fmaf(pr[j].x, br[4 * j + 0], acc);
                    acc = fmaf(pr[j].y, br[4 * j + 1], acc);
                    acc = fmaf(pr[j].z, br[4 * j + 2], acc);
                    acc = fmaf(pr[j].w, br[4 * j + 3], acc);
                }
                g_lut[ck * NM + m] = acc;
            }
        }
        __syncthreads();
        if (tid == 0) { __threadfence(); g_lut_ready = 1; }
        return;
    }

    // ---- tile block ----
    const long long base = (long long)(blockIdx.x - 1) * TB;

    // stage A: warp = 4 rows x 8 chunks; coalesced LDG.128, conflict-free STS
    {
        const int w = tid >> 5, lane = tid & 31;
        const int dr = lane >> 3, c8 = lane & 7;
        const float4* gb = (const float4*)(A + base * ND);
#pragma unroll
        for (int jr = 0; jr < 8; jr++) {
            int r = jr * 16 + w * 4 + dr;
            bool ok = (base + r < N);
#pragma unroll
            for (int jc = 0; jc < 2; jc++) {
                int c4 = jc * 8 + c8;
                if (ok) {
                    float4 v = gb[r * 16 + c4];
                    float* p = As + r * NDP + (c4 << 2);
                    p[0] = v.x; p[1] = v.y; p[2] = v.z; p[3] = v.w;
                }
            }
        }
    }

    // stage repacked split-vals + dims
    for (int i = tid; i < NC * 16; i += TB) {
        int cb = i >> 4, j = i & 15;
        int src = (j == 0) ? 0 : (j == 1) ? 8 : (j == 2) ? 9 : (j == 3) ? 0
                : (j < 8) ? (12 + j) : (16 + j);
        sval16[i] = sval_g[cb * 32 + src];
    }
    if (tid < NC * NSPL) sdim[tid] = sdim_g[tid];
    __syncthreads();

    const bool active = (base + tid < N);

    // ---- encode (code kept in register; no global roundtrip) ----
    unsigned long long code = 0ull;
    if (active) {
        const float* arow = As + tid * NDP;
#pragma unroll
        for (int c = 0; c < NC; c++) {
            const int4   sd  = ((const int4*)sdim)[c];
            const float4 q0  = ((const float4*)sval16)[c * 4 + 0]; // s0,s1x,s1y,pad
            const float4 s2  = ((const float4*)sval16)[c * 4 + 1];
            const float4 s3a = ((const float4*)sval16)[c * 4 + 2];
            const float4 s3b = ((const float4*)sval16)[c * 4 + 3];

            const float x0 = arow[sd.x];
            const float x1 = arow[sd.y];
            const float x2 = arow[sd.z];
            const float x3 = arow[sd.w];

            const bool  b0 = x0 > q0.x;
            const float v1 = b0 ? q0.z : q0.y;
            const bool  b1 = x1 > v1;
            const float t0 = b0 ? s2.z : s2.x;
            const float t1 = b0 ? s2.w : s2.y;
            const float v2 = b1 ? t1 : t0;
            const bool  b2 = x2 > v2;
            const float u0 = b0 ? s3b.x : s3a.x;
            const float u1 = b0 ? s3b.y : s3a.y;
            const float u2 = b0 ? s3b.z : s3a.z;
            const float u3 = b0 ? s3b.w : s3a.w;
            const float w0 = b1 ? u2 : u0;
            const float w1 = b1 ? u3 : u1;
            const float v3 = b2 ? w1 : w0;
            const bool  b3 = x3 > v3;

            const unsigned long long g =
                (unsigned long long)((((((int)b0 << 1) | (int)b1) << 1) | (int)b2) << 1 | (int)b3);
            code |= g << (4 * c);
        }
    }

    // ---- wait for LUT, then stage it (stride-20 remap) ----
    if (tid == 0) {
        while (g_lut_ready == 0) __nanosleep(200);
        __threadfence();
    }
    __syncthreads();
#pragma unroll
    for (int j = 0; j < 32; j++) {
        int i = j * TB + tid;                    // 0..4095
        lut_s[(i >> 4) * LSTR + (i & 15)] = g_lut[i];
    }
    __syncthreads();

    // ---- gather ----
    if (!active) return;

    unsigned long long acc[8];
#pragma unroll
    for (int j = 0; j < 8; j++) acc[j] = 0ull;

#pragma unroll
    for (int c = 0; c < NC; c++) {
        const int g = (int)((code >> (4 * c)) & 15ull);
        const ulonglong2* lr = (const ulonglong2*)(lut_s + (c * NK + g) * LSTR);
#pragma unroll
        for (int j = 0; j < 4; j++) {
            ulonglong2 v = lr[j];
            fadd2(acc[2 * j],     v.x);
            fadd2(acc[2 * j + 1], v.y);
        }
    }

    const long long n = base + tid;
    const long long Nll = N;
    const float2* accf = (const float2*)acc;
#pragma unroll
    for (int j = 0; j < 8; j++) {
        float2 p = accf[j];
        out[(long long)(2 * j)     * Nll + n] = p.x;
        out[(long long)(2 * j + 1) * Nll + n] = p.y;
    }
}

// ---------------------------------------------------------------------------
extern "C" void kernel_launch(void* const* d_in, const int* in_sizes, int n_in,
                              void* d_out, int out_size) {
    const float* A     = (const float*)d_in[0];
    const float* B     = (const float*)d_in[1];
    const float* P     = (const float*)d_in[2];
    const int*   sdims = (const int*)d_in[3];
    const float* svals = (const float*)d_in[4];
    float* out = (float*)d_out;
    int N = in_sizes[0] / ND;
    int ntiles = (N + TB - 1) / TB;

    size_t smem_bytes = (size_t)(TB * NDP + NC * NK * LSTR + NC * 16) * 4
                      + (size_t)(NC * NSPL) * 4;               // 55040 B
    cudaFuncSetAttribute(fused_kernel,
                         cudaFuncAttributeMaxDynamicSharedMemorySize,
                         (int)smem_bytes);

    fused_kernel<<<ntiles + 1, TB, smem_bytes>>>(A, B, P, sdims, svals, out, N);
}

// round 8
// speedup vs baseline: 1.2128x; 1.2128x over previous
#include <cuda_runtime.h>

#define NC 16       // codebooks
#define NK 16       // prototypes per codebook
#define NM 16       // output rows (M)
#define ND 64       // feature dim
#define NDP 65      // padded A row stride: bank=(r+d)%32 -> conflict-free encode reads
#define NSPL 4      // tree depth
#define LSTR 20     // LUT row stride: conflict-free LDS.128 gather
#define TBE 128     // encode: rows per tile
#define TBG 256     // gather: threads = rows per tile

__device__ float g_lut[NC * NK * NM];
__device__ unsigned long long g_codes[1 << 18];   // 262144 rows, 2MB

__device__ __forceinline__ void fadd2(unsigned long long& a, unsigned long long b) {
    asm("add.rn.f32x2 %0, %0, %1;" : "+l"(a) : "l"(b));
}

// ---------------------------------------------------------------------------
// Kernel A (encode + lut fused in one launch):
//   blocks [0, ntiles)        : encode 128 rows -> packed 64-bit code/row
//   blocks [ntiles, ntiles+16): lut[c,k,m] = sum_d B[m,d]*P[c,k,d]
// ---------------------------------------------------------------------------
__global__ void __launch_bounds__(TBE, 6) encode_kernel(
    const float* __restrict__ A,
    const float* __restrict__ B,        // [M,D]
    const float* __restrict__ P,        // [C,K,D]
    const int*   __restrict__ sdim_g,   // [C,NSPL]
    const float* __restrict__ sval_g,   // [C,NSPL,8]
    int N, int ntiles)
{
    __shared__ float As[TBE * NDP];       // 33280B (reused as Bs/Ps by lut blocks)
    __shared__ float sval16[NC * 16];
    __shared__ int   sdim[NC * NSPL];

    const int tid = threadIdx.x;

    if (blockIdx.x >= ntiles) {
        // ---- LUT block: one codebook c ----
        int c = blockIdx.x - ntiles;
        float* Bs = As;                       // [NM][ND+1]
        float* Ps = As + NM * (ND + 1);       // [NK][ND+1]
        for (int i = tid; i < NM * ND; i += TBE) Bs[(i >> 6) * (ND + 1) + (i & 63)] = B[i];
        for (int i = tid; i < NK * ND; i += TBE) Ps[(i >> 6) * (ND + 1) + (i & 63)] = P[c * NK * ND + i];
        __syncthreads();
#pragma unroll
        for (int e = 0; e < 2; e++) {
            int i = e * TBE + tid;            // 0..255
            int k = i >> 4, m = i & 15;
            float acc = 0.f;
#pragma unroll
            for (int d = 0; d < ND; d++)
                acc = fmaf(Bs[m * (ND + 1) + d], Ps[k * (ND + 1) + d], acc);
            g_lut[(c * NK + k) * NM + m] = acc;
        }
        return;
    }

    const long long base = (long long)blockIdx.x * TBE;

    // --- stage A: warp = 4 rows x 8 chunks; coalesced LDG.128, conflict-free STS ---
    {
        const int w = tid >> 5, lane = tid & 31;
        const int dr = lane >> 3, c8 = lane & 7;
        const float4* gb = (const float4*)(A + base * ND);
#pragma unroll
        for (int jr = 0; jr < 8; jr++) {
            int r = jr * 16 + w * 4 + dr;
            bool ok = (base + r < N);
#pragma unroll
            for (int jc = 0; jc < 2; jc++) {
                int c4 = jc * 8 + c8;
                if (ok) {
                    float4 v = gb[r * 16 + c4];
                    float* p = As + r * NDP + (c4 << 2);
                    p[0] = v.x; p[1] = v.y; p[2] = v.z; p[3] = v.w;
                }
            }
        }
    }

    // --- stage repacked split-vals + dims ---
    for (int i = tid; i < NC * 16; i += TBE) {
        int cb = i >> 4, j = i & 15;
        int src = (j == 0) ? 0 : (j == 1) ? 8 : (j == 2) ? 9 : (j == 3) ? 0
                : (j < 8) ? (12 + j) : (16 + j);
        sval16[i] = sval_g[cb * 32 + src];
    }
    if (tid < NC * NSPL) sdim[tid] = sdim_g[tid];
    __syncthreads();

    const int r = tid;
    if (base + r >= N) return;
    const float* arow = As + r * NDP;

    unsigned long long code = 0ull;
#pragma unroll
    for (int c = 0; c < NC; c++) {
        const int4   sd  = ((const int4*)sdim)[c];
        const float4 q0  = ((const float4*)sval16)[c * 4 + 0]; // s0, s1x, s1y, pad
        const float4 s2  = ((const float4*)sval16)[c * 4 + 1];
        const float4 s3a = ((const float4*)sval16)[c * 4 + 2];
        const float4 s3b = ((const float4*)sval16)[c * 4 + 3];

        const float x0 = arow[sd.x];
        const float x1 = arow[sd.y];
        const float x2 = arow[sd.z];
        const float x3 = arow[sd.w];

        const bool  b0 = x0 > q0.x;
        const float v1 = b0 ? q0.z : q0.y;
        const bool  b1 = x1 > v1;
        const float t0 = b0 ? s2.z : s2.x;
        const float t1 = b0 ? s2.w : s2.y;
        const float v2 = b1 ? t1 : t0;
        const bool  b2 = x2 > v2;
        const float u0 = b0 ? s3b.x : s3a.x;
        const float u1 = b0 ? s3b.y : s3a.y;
        const float u2 = b0 ? s3b.z : s3a.z;
        const float u3 = b0 ? s3b.w : s3a.w;
        const float w0 = b1 ? u2 : u0;
        const float w1 = b1 ? u3 : u1;
        const float v3 = b2 ? w1 : w0;
        const bool  b3 = x3 > v3;

        const unsigned long long g =
            (unsigned long long)((((((int)b0 << 1) | (int)b1) << 1) | (int)b2) << 1 | (int)b3);
        code |= g << (4 * c);
    }
    g_codes[base + r] = code;
}

// ---------------------------------------------------------------------------
// Kernel B (gather): 1 row/thread, TBG=256, 5 CTAs/SM -> 40 warps/SM.
// LUT-only smem (20.5KB); float4 staging; conflict-free LDS.128 gather;
// packed f32x2 accumulate.
// ---------------------------------------------------------------------------
__global__ void __launch_bounds__(TBG, 5) gather_kernel(
    float* __restrict__ out, int N)
{
    __shared__ float lut_s[NC * NK * LSTR];   // 20480B

    const int tid = threadIdx.x;
    const long long n = (long long)blockIdx.x * TBG + tid;
    const bool ok = n < N;

    // hoist the code load: no smem dependency, overlaps staging
    const unsigned long long code = ok ? g_codes[n] : 0ull;

    // stage LUT: 4 x LDG.128 per thread, stride-20 remap STS
    {
        const float4* gl = (const float4*)g_lut;
#pragma unroll
        for (int j = 0; j < 4; j++) {
            int i4 = j * TBG + tid;            // 0..1023 (float4 index)
            float4 v = gl[i4];
            int ck = i4 >> 2;                  // LUT row (c*16+k)
            int m0 = (i4 & 3) << 2;            // starting m
            float* p = lut_s + ck * LSTR + m0;
            p[0] = v.x; p[1] = v.y; p[2] = v.z; p[3] = v.w;
        }
    }
    __syncthreads();

    if (!ok) return;

    unsigned long long acc[8];
#pragma unroll
    for (int j = 0; j < 8; j++) acc[j] = 0ull;

#pragma unroll
    for (int c = 0; c < NC; c++) {
        const int g = (int)((code >> (4 * c)) & 15ull);
        const ulonglong2* lr = (const ulonglong2*)(lut_s + (c * NK + g) * LSTR);
#pragma unroll
        for (int j = 0; j < 4; j++) {
            ulonglong2 v = lr[j];
            fadd2(acc[2 * j],     v.x);
            fadd2(acc[2 * j + 1], v.y);
        }
    }

    const long long Nll = N;
    const float2* accf = (const float2*)acc;
#pragma unroll
    for (int j = 0; j < 8; j++) {
        float2 p = accf[j];
        out[(long long)(2 * j)     * Nll + n] = p.x;
        out[(long long)(2 * j + 1) * Nll + n] = p.y;
    }
}

// ---------------------------------------------------------------------------
extern "C" void kernel_launch(void* const* d_in, const int* in_sizes, int n_in,
                              void* d_out, int out_size) {
    const float* A     = (const float*)d_in[0];
    const float* B     = (const float*)d_in[1];
    const float* P     = (const float*)d_in[2];
    const int*   sdims = (const int*)d_in[3];
    const float* svals = (const float*)d_in[4];
    float* out = (float*)d_out;
    int N = in_sizes[0] / ND;

    int ntiles = (N + TBE - 1) / TBE;
    encode_kernel<<<ntiles + NC, TBE>>>(A, B, P, sdims, svals, N, ntiles);
    gather_kernel<<<(N + TBG - 1) / TBG, TBG>>>(out, N);
}

// round 9
// speedup vs baseline: 1.3952x; 1.1504x over previous
#include <cuda_runtime.h>
#include <cuda_fp16.h>

#define NC 16       // codebooks
#define NK 16       // prototypes per codebook
#define NM 16       // output rows (M)
#define ND 64       // feature dim
#define NDP 65      // padded A row stride: bank=(r+d)%32 -> conflict-free encode reads
#define NSPL 4      // tree depth
#define HSTR 24     // fp16 LUT row stride in halves (48B, 16B-aligned; quad-bank 3g+j spreads)
#define TBE 128     // encode: rows per tile
#define TBG 256     // gather: threads = rows per tile

__device__ __half         g_lut_h[NC * NK * NM];    // fp16 LUT (8KB)
__device__ unsigned long long g_codes[1 << 18];     // 262144 rows, 2MB

// ---------------------------------------------------------------------------
// Kernel A (encode + lut fused in one launch):
//   blocks [0, ntiles)        : encode 128 rows -> packed 64-bit code/row
//   blocks [ntiles, ntiles+16): lut[c,k,m] = sum_d B[m,d]*P[c,k,d] (fp32 dot,
//                               stored fp16)
// ---------------------------------------------------------------------------
__global__ void __launch_bounds__(TBE, 6) encode_kernel(
    const float* __restrict__ A,
    const float* __restrict__ B,        // [M,D]
    const float* __restrict__ P,        // [C,K,D]
    const int*   __restrict__ sdim_g,   // [C,NSPL]
    const float* __restrict__ sval_g,   // [C,NSPL,8]
    int N, int ntiles)
{
    __shared__ float As[TBE * NDP];       // 33280B (reused as Bs/Ps by lut blocks)
    __shared__ float sval16[NC * 16];
    __shared__ int   sdim[NC * NSPL];

    const int tid = threadIdx.x;

    if (blockIdx.x >= ntiles) {
        // ---- LUT block: one codebook c ----
        int c = blockIdx.x - ntiles;
        float* Bs = As;                       // [NM][ND+1]
        float* Ps = As + NM * (ND + 1);       // [NK][ND+1]
        for (int i = tid; i < NM * ND; i += TBE) Bs[(i >> 6) * (ND + 1) + (i & 63)] = B[i];
        for (int i = tid; i < NK * ND; i += TBE) Ps[(i >> 6) * (ND + 1) + (i & 63)] = P[c * NK * ND + i];
        __syncthreads();
#pragma unroll
        for (int e = 0; e < 2; e++) {
            int i = e * TBE + tid;            // 0..255
            int k = i >> 4, m = i & 15;
            float acc = 0.f;
#pragma unroll
            for (int d = 0; d < ND; d++)
                acc = fmaf(Bs[m * (ND + 1) + d], Ps[k * (ND + 1) + d], acc);
            g_lut_h[(c * NK + k) * NM + m] = __float2half_rn(acc);
        }
        return;
    }

    const long long base = (long long)blockIdx.x * TBE;

    // --- stage A: warp = 4 rows x 8 chunks; coalesced LDG.128, conflict-free STS ---
    {
        const int w = tid >> 5, lane = tid & 31;
        const int dr = lane >> 3, c8 = lane & 7;
        const float4* gb = (const float4*)(A + base * ND);
#pragma unroll
        for (int jr = 0; jr < 8; jr++) {
            int r = jr * 16 + w * 4 + dr;
            bool ok = (base + r < N);
#pragma unroll
            for (int jc = 0; jc < 2; jc++) {
                int c4 = jc * 8 + c8;
                if (ok) {
                    float4 v = gb[r * 16 + c4];
                    float* p = As + r * NDP + (c4 << 2);
                    p[0] = v.x; p[1] = v.y; p[2] = v.z; p[3] = v.w;
                }
            }
        }
    }

    // --- stage repacked split-vals + dims ---
    for (int i = tid; i < NC * 16; i += TBE) {
        int cb = i >> 4, j = i & 15;
        int src = (j == 0) ? 0 : (j == 1) ? 8 : (j == 2) ? 9 : (j == 3) ? 0
                : (j < 8) ? (12 + j) : (16 + j);
        sval16[i] = sval_g[cb * 32 + src];
    }
    if (tid < NC * NSPL) sdim[tid] = sdim_g[tid];
    __syncthreads();

    const int r = tid;
    if (base + r >= N) return;
    const float* arow = As + r * NDP;

    unsigned long long code = 0ull;
#pragma unroll
    for (int c = 0; c < NC; c++) {
        const int4   sd  = ((const int4*)sdim)[c];
        const float4 q0  = ((const float4*)sval16)[c * 4 + 0]; // s0, s1x, s1y, pad
        const float4 s2  = ((const float4*)sval16)[c * 4 + 1];
        const float4 s3a = ((const float4*)sval16)[c * 4 + 2];
        const float4 s3b = ((const float4*)sval16)[c * 4 + 3];

        const float x0 = arow[sd.x];
        const float x1 = arow[sd.y];
        const float x2 = arow[sd.z];
        const float x3 = arow[sd.w];

        const bool  b0 = x0 > q0.x;
        const float v1 = b0 ? q0.z : q0.y;
        const bool  b1 = x1 > v1;
        const float t0 = b0 ? s2.z : s2.x;
        const float t1 = b0 ? s2.w : s2.y;
        const float v2 = b1 ? t1 : t0;
        const bool  b2 = x2 > v2;
        const float u0 = b0 ? s3b.x : s3a.x;
        const float u1 = b0 ? s3b.y : s3a.y;
        const float u2 = b0 ? s3b.z : s3a.z;
        const float u3 = b0 ? s3b.w : s3a.w;
        const float w0 = b1 ? u2 : u0;
        const float w1 = b1 ? u3 : u1;
        const float v3 = b2 ? w1 : w0;
        const bool  b3 = x3 > v3;

        const unsigned long long g =
            (unsigned long long)((((((int)b0 << 1) | (int)b1) << 1) | (int)b2) << 1 | (int)b3);
        code |= g << (4 * c);
    }
    g_codes[base + r] = code;
}

// ---------------------------------------------------------------------------
// Kernel B (gather): fp16 LUT in smem (12.3KB, stride-24-half rows), 5 CTAs/SM.
// Per cb: 2 x LDS.128 (8 halves each, ~2wf with gid dedupe), unpack to fp32,
// accumulate fp32. Halves L1 wavefront traffic vs fp32 LUT.
// ---------------------------------------------------------------------------
__global__ void __launch_bounds__(TBG, 5) gather_kernel(
    float* __restrict__ out, int N)
{
    __shared__ __align__(16) __half lut16[NC * NK * HSTR];   // 12288B

    const int tid = threadIdx.x;
    const long long n = (long long)blockIdx.x * TBG + tid;
    const bool ok = n < N;

    // hoist the code load: no smem dependency, overlaps staging
    const unsigned long long code = ok ? g_codes[n] : 0ull;

    // stage LUT: 512 16B-chunks; thread does chunks tid and tid+256
    {
        const uint4* gl = (const uint4*)g_lut_h;
        uint4* ls = (uint4*)lut16;
#pragma unroll
        for (int s = 0; s < 2; s++) {
            int ch = s * TBG + tid;           // 0..511
            int row = ch >> 1, h = ch & 1;    // LUT row, 16B half-of-row
            ls[row * 3 + h] = gl[ch];         // HSTR=24 halves = 3 uint4
        }
    }
    __syncthreads();

    if (!ok) return;

    float2 acc[8];
#pragma unroll
    for (int j = 0; j < 8; j++) { acc[j].x = 0.f; acc[j].y = 0.f; }

#pragma unroll
    for (int c = 0; c < NC; c++) {
        const int g = (int)((code >> (4 * c)) & 15ull);
        const uint4* lr = (const uint4*)(lut16 + (c * NK + g) * HSTR);
        uint4 a = lr[0];                       // m 0..7
        uint4 b = lr[1];                       // m 8..15
        const __half2* ah = (const __half2*)&a;
        const __half2* bh = (const __half2*)&b;
#pragma unroll
        for (int k = 0; k < 4; k++) {
            float2 fa = __half22float2(ah[k]);
            float2 fb = __half22float2(bh[k]);
            acc[k].x     += fa.x; acc[k].y     += fa.y;
            acc[4 + k].x += fb.x; acc[4 + k].y += fb.y;
        }
    }

    const long long Nll = N;
#pragma unroll
    for (int j = 0; j < 8; j++) {
        out[(long long)(2 * j)     * Nll + n] = acc[j].x;
        out[(long long)(2 * j + 1) * Nll + n] = acc[j].y;
    }
}

// ---------------------------------------------------------------------------
extern "C" void kernel_launch(void* const* d_in, const int* in_sizes, int n_in,
                              void* d_out, int out_size) {
    const float* A     = (const float*)d_in[0];
    const float* B     = (const float*)d_in[1];
    const float* P     = (const float*)d_in[2];
    const int*   sdims = (const int*)d_in[3];
    const float* svals = (const float*)d_in[4];
    float* out = (float*)d_out;
    int N = in_sizes[0] / ND;

    int ntiles = (N + TBE - 1) / TBE;
    encode_kernel<<<ntiles + NC, TBE>>>(A, B, P, sdims, svals, N, ntiles);
    gather_kernel<<<(N + TBG - 1) / TBG, TBG>>>(out, N);
}

// round 10
// speedup vs baseline: 1.4576x; 1.0447x over previous
#include <cuda_runtime.h>
#include <cuda_fp16.h>

#define NC 16       // codebooks
#define NK 16       // prototypes per codebook
#define NM 16       // output rows (M)
#define ND 64       // feature dim
#define NDP 65      // padded A row stride: bank=(r+d)%32 -> conflict-free encode reads
#define NSPL 4      // tree depth
#define HSTR 24     // fp16 LUT row stride in halves (48B, 16B-aligned)
#define TBE 128     // encode: rows per tile
#define TBG 256     // gather: threads = rows per tile

__device__ __half             g_lut_h[NC * NK * NM];   // fp16 LUT (8KB)
__device__ unsigned long long g_codes[1 << 18];        // 262144 rows, 2MB

// ---------------------------------------------------------------------------
// Kernel A (encode + lut fused in one launch):
//   blocks [0, ntiles)        : encode 128 rows -> packed 64-bit code/row
//   blocks [ntiles, ntiles+16): lut[c,k,m] = sum_d B[m,d]*P[c,k,d] (fp32 dot,
//                               stored fp16)
// Encode staging is WARP-AUTONOMOUS: each warp stages its own 32 rows and
// syncs only via __syncwarp -> no block-wide convoy on DRAM latency.
// ---------------------------------------------------------------------------
__global__ void __launch_bounds__(TBE, 6) encode_kernel(
    const float* __restrict__ A,
    const float* __restrict__ B,        // [M,D]
    const float* __restrict__ P,        // [C,K,D]
    const int*   __restrict__ sdim_g,   // [C,NSPL]
    const float* __restrict__ sval_g,   // [C,NSPL,8]
    int N, int ntiles)
{
    __shared__ float As[TBE * NDP];       // 33280B (reused as Bs/Ps by lut blocks)
    __shared__ float sval16[NC * 16];
    __shared__ int   sdim[NC * NSPL];

    const int tid = threadIdx.x;

    if (blockIdx.x >= ntiles) {
        // ---- LUT block: one codebook c ----
        int c = blockIdx.x - ntiles;
        float* Bs = As;                       // [NM][ND+1]
        float* Ps = As + NM * (ND + 1);       // [NK][ND+1]
        for (int i = tid; i < NM * ND; i += TBE) Bs[(i >> 6) * (ND + 1) + (i & 63)] = B[i];
        for (int i = tid; i < NK * ND; i += TBE) Ps[(i >> 6) * (ND + 1) + (i & 63)] = P[c * NK * ND + i];
        __syncthreads();
#pragma unroll
        for (int e = 0; e < 2; e++) {
            int i = e * TBE + tid;            // 0..255
            int k = i >> 4, m = i & 15;
            float acc = 0.f;
#pragma unroll
            for (int d = 0; d < ND; d++)
                acc = fmaf(Bs[m * (ND + 1) + d], Ps[k * (ND + 1) + d], acc);
            g_lut_h[(c * NK + k) * NM + m] = __float2half_rn(acc);
        }
        return;
    }

    const long long base = (long long)blockIdx.x * TBE;
    const int w = tid >> 5, lane = tid & 31;

    // --- stage small tables first; the block barrier here is cheap because
    //     no DRAM-latency work precedes it ---
    for (int i = tid; i < NC * 16; i += TBE) {
        int cb = i >> 4, j = i & 15;
        int src = (j == 0) ? 0 : (j == 1) ? 8 : (j == 2) ? 9 : (j == 3) ? 0
                : (j < 8) ? (12 + j) : (16 + j);
        sval16[i] = sval_g[cb * 32 + src];
    }
    if (tid < NC * NSPL) sdim[tid] = sdim_g[tid];
    __syncthreads();

    // --- warp-autonomous A staging: warp w stages rows [w*32, w*32+32).
    //     Same conflict-free mapping (4 rows x 8 chunks per instruction),
    //     coalesced 4x128B LDG segments. Only __syncwarp needed. ---
    {
        const int dr = lane >> 3, c8 = lane & 7;
        const float4* gb = (const float4*)(A + base * ND);
#pragma unroll
        for (int jr = 0; jr < 8; jr++) {
            int r = w * 32 + jr * 4 + dr;
            bool okr = (base + r < N);
#pragma unroll
            for (int jc = 0; jc < 2; jc++) {
                int c4 = jc * 8 + c8;
                if (okr) {
                    float4 v = gb[r * 16 + c4];
                    float* p = As + r * NDP + (c4 << 2);
                    p[0] = v.x; p[1] = v.y; p[2] = v.z; p[3] = v.w;
                }
            }
        }
    }
    __syncwarp();

    const int r = tid;                      // warp w encodes rows it staged
    if (base + r >= N) return;
    const float* arow = As + r * NDP;

    unsigned long long code = 0ull;
#pragma unroll
    for (int c = 0; c < NC; c++) {
        const int4   sd  = ((const int4*)sdim)[c];
        const float4 q0  = ((const float4*)sval16)[c * 4 + 0]; // s0, s1x, s1y, pad
        const float4 s2  = ((const float4*)sval16)[c * 4 + 1];
        const float4 s3a = ((const float4*)sval16)[c * 4 + 2];
        const float4 s3b = ((const float4*)sval16)[c * 4 + 3];

        const float x0 = arow[sd.x];
        const float x1 = arow[sd.y];
        const float x2 = arow[sd.z];
        const float x3 = arow[sd.w];

        const bool  b0 = x0 > q0.x;
        const float v1 = b0 ? q0.z : q0.y;
        const bool  b1 = x1 > v1;
        const float t0 = b0 ? s2.z : s2.x;
        const float t1 = b0 ? s2.w : s2.y;
        const float v2 = b1 ? t1 : t0;
        const bool  b2 = x2 > v2;
        const float u0 = b0 ? s3b.x : s3a.x;
        const float u1 = b0 ? s3b.y : s3a.y;
        const float u2 = b0 ? s3b.z : s3a.z;
        const float u3 = b0 ? s3b.w : s3a.w;
        const float w0 = b1 ? u2 : u0;
        const float w1 = b1 ? u3 : u1;
        const float v3 = b2 ? w1 : w0;
        const bool  b3 = x3 > v3;

        const unsigned long long g =
            (unsigned long long)((((((int)b0 << 1) | (int)b1) << 1) | (int)b2) << 1 | (int)b3);
        code |= g << (4 * c);
    }
    g_codes[base + r] = code;
}

// ---------------------------------------------------------------------------
// Kernel B (gather): fp16 LUT in smem (12.3KB, stride-24-half rows), 5 CTAs/SM.
// Per cb: 2 x LDS.128, unpack to fp32, accumulate fp32.
// ---------------------------------------------------------------------------
__global__ void __launch_bounds__(TBG, 5) gather_kernel(
    float* __restrict__ out, int N)
{
    __shared__ __align__(16) __half lut16[NC * NK * HSTR];   // 12288B

    const int tid = threadIdx.x;
    const long long n = (long long)blockIdx.x * TBG + tid;
    const bool ok = n < N;

    // hoist the code load: no smem dependency, overlaps staging
    const unsigned long long code = ok ? g_codes[n] : 0ull;

    // stage LUT: 512 16B-chunks; thread does chunks tid and tid+256
    {
        const uint4* gl = (const uint4*)g_lut_h;
        uint4* ls = (uint4*)lut16;
#pragma unroll
        for (int s = 0; s < 2; s++) {
            int ch = s * TBG + tid;           // 0..511
            int row = ch >> 1, h = ch & 1;    // LUT row, 16B half-of-row
            ls[row * 3 + h] = gl[ch];         // HSTR=24 halves = 3 uint4
        }
    }
    __syncthreads();

    if (!ok) return;

    float2 acc[8];
#pragma unroll
    for (int j = 0; j < 8; j++) { acc[j].x = 0.f; acc[j].y = 0.f; }

#pragma unroll
    for (int c = 0; c < NC; c++) {
        const int g = (int)((code >> (4 * c)) & 15ull);
        const uint4* lr = (const uint4*)(lut16 + (c * NK + g) * HSTR);
        uint4 a = lr[0];                       // m 0..7
        uint4 b = lr[1];                       // m 8..15
        const __half2* ah = (const __half2*)&a;
        const __half2* bh = (const __half2*)&b;
#pragma unroll
        for (int k = 0; k < 4; k++) {
            float2 fa = __half22float2(ah[k]);
            float2 fb = __half22float2(bh[k]);
            acc[k].x     += fa.x; acc[k].y     += fa.y;
            acc[4 + k].x += fb.x; acc[4 + k].y += fb.y;
        }
    }

    const long long Nll = N;
#pragma unroll
    for (int j = 0; j < 8; j++) {
        out[(long long)(2 * j)     * Nll + n] = acc[j].x;
        out[(long long)(2 * j + 1) * Nll + n] = acc[j].y;
    }
}

// ---------------------------------------------------------------------------
extern "C" void kernel_launch(void* const* d_in, const int* in_sizes, int n_in,
                              void* d_out, int out_size) {
    const float* A     = (const float*)d_in[0];
    const float* B     = (const float*)d_in[1];
    const float* P     = (const float*)d_in[2];
    const int*   sdims = (const int*)d_in[3];
    const float* svals = (const float*)d_in[4];
    float* out = (float*)d_out;
    int N = in_sizes[0] / ND;

    int ntiles = (N + TBE - 1) / TBE;
    encode_kernel<<<ntiles + NC, TBE>>>(A, B, P, sdims, svals, N, ntiles);
    gather_kernel<<<(N + TBG - 1) / TBG, TBG>>>(out, N);
}